// round 6
// baseline (speedup 1.0000x reference)
#include <cuda_runtime.h>
#include <math.h>

// ---------------- global scratch (allocation-free rule) ----------------
static __device__ float2 g_p1[4096 * 845];   // L1 pooled output as {silu, t}
static __device__ float2 g_p2[4096 * 405];   // L2 output as {silu, t}
static __device__ float  g_h[4096 * 98];     // L3 conv output (flattened)

// fp32 cubic-coefficient tables: entry (row, j) = float4(c0,c1,c2,c3), j in [0,10]
static __device__ float4 g_c1[45 * 11];
static __device__ float4 g_c2[625 * 11];     // row = o*125 + f
static __device__ float4 g_c3[90 * 11];
// transposed base weights
static __device__ float g_wbT1[9 * 8];       // f*8 + o (o<5)
static __device__ float g_wbT2s[2 * 500];    // half*500 + f*4 + o'  (A: o0..2, B: o3..4)
static __device__ float g_wbT3[45 * 8];      // f*8 + o (o<2)

__device__ __forceinline__ float silu_f(float x) {
    return __fdividef(x, 1.0f + __expf(-x));
}
__device__ __forceinline__ float tmap(float x) { return (x + 1.0f) * 2.5f + 3.0f; }
__device__ __forceinline__ float cubic4(float4 q, float u) {
    return ((q.w * u + q.z) * u + q.y) * u + q.x;
}

// ---------------- setup ----------------
__device__ __forceinline__ float4 coef_from_w(const float* __restrict__ ws, int row, int j) {
    float w[4];
#pragma unroll
    for (int k = 0; k < 4; k++) {
        int g = j - 3 + k;
        w[k] = (g >= 0 && g <= 7) ? ws[row * 8 + g] : 0.0f;
    }
    const float s6 = 1.0f / 6.0f;
    float4 c;
    c.x = (w[0] + 4.0f * w[1] + w[2]) * s6;
    c.y = (w[2] - w[0]) * 0.5f;
    c.z = (w[0] - 2.0f * w[1] + w[2]) * 0.5f;
    c.w = (-w[0] + 3.0f * w[1] - 3.0f * w[2] + w[3]) * s6;
    return c;
}

__global__ void build_tables(const float* __restrict__ ws1, const float* __restrict__ ws2,
                             const float* __restrict__ ws3, const float* __restrict__ wb1,
                             const float* __restrict__ wb2, const float* __restrict__ wb3) {
    int stride = gridDim.x * blockDim.x;
    int tid = blockIdx.x * blockDim.x + threadIdx.x;
    for (int i = tid; i < 45 * 11; i += stride) g_c1[i] = coef_from_w(ws1, i / 11, i % 11);
    for (int i = tid; i < 625 * 11; i += stride) g_c2[i] = coef_from_w(ws2, i / 11, i % 11);
    for (int i = tid; i < 90 * 11; i += stride) g_c3[i] = coef_from_w(ws3, i / 11, i % 11);
    for (int i = tid; i < 9 * 8; i += stride) {
        int f = i / 8, o = i % 8;
        g_wbT1[i] = (o < 5) ? wb1[o * 9 + f] : 0.0f;
    }
    for (int i = tid; i < 500; i += stride) {          // half A: o 0..2
        int f = i / 4, o = i % 4;
        g_wbT2s[i] = (o < 3) ? wb2[o * 125 + f] : 0.0f;
    }
    for (int i = tid; i < 500; i += stride) {          // half B: o 3..4
        int f = i / 4, o = i % 4;
        g_wbT2s[500 + i] = (o < 2) ? wb2[(o + 3) * 125 + f] : 0.0f;
    }
    for (int i = tid; i < 45 * 8; i += stride) {
        int f = i / 8, o = i % 8;
        g_wbT3[i] = (o < 2) ? wb3[o * 45 + f] : 0.0f;
    }
}

// ---------------- Kernel 1: conv3(Cin=1,O=5) + maxpool2, 3 imgs/block ----------------
#define K1_IMGS 3
__global__ void __launch_bounds__(256)
k1_conv_pool(const float* __restrict__ x, int B) {
    __shared__ __align__(16) float wbTs[9 * 8];
    __shared__ float4 c1s[45 * 11];
    __shared__ float2 px[K1_IMGS * 784];
    int tid = threadIdx.x;
    int b0 = blockIdx.x * K1_IMGS;
    int nimg = min(K1_IMGS, B - b0);

    for (int i = tid; i < 45 * 11; i += 256) c1s[i] = g_c1[i];
    if (tid < 72) wbTs[tid] = g_wbT1[tid];
    for (int i = tid; i < nimg * 784; i += 256) {
        float v = x[b0 * 784 + i];
        px[i] = make_float2(silu_f(v), tmap(v));
    }
    __syncthreads();

    for (int task = tid; task < nimg * 169; task += 256) {
        int li = task / 169, p = task % 169;
        int ph = p / 13, pw = p % 13;
        float best[5];
#pragma unroll
        for (int o = 0; o < 5; o++) best[o] = -3.0e38f;

        for (int d = 0; d < 4; d++) {
            int y = 2 * ph + (d >> 1), xx = 2 * pw + (d & 1);
            float a0 = 0, a1 = 0, a2 = 0, a3 = 0, a4 = 0;
#pragma unroll
            for (int r = 0; r < 3; r++)
#pragma unroll
            for (int c = 0; c < 3; c++) {
                int f = r * 3 + c;
                float2 st = px[li * 784 + (y + r) * 28 + xx + c];
                float4 wbv = *reinterpret_cast<const float4*>(&wbTs[f * 8]);
                float wb4 = wbTs[f * 8 + 4];
                a0 += st.x * wbv.x; a1 += st.x * wbv.y; a2 += st.x * wbv.z;
                a3 += st.x * wbv.w; a4 += st.x * wb4;
                float fj = floorf(st.y);
                int j = (int)fj;
                float u = st.y - fj;
                if ((unsigned)j <= 10u) {
                    int i0 = f * 11 + j;
                    a0 += cubic4(c1s[i0], u);
                    a1 += cubic4(c1s[i0 + 99], u);
                    a2 += cubic4(c1s[i0 + 198], u);
                    a3 += cubic4(c1s[i0 + 297], u);
                    a4 += cubic4(c1s[i0 + 396], u);
                }
            }
            best[0] = fmaxf(best[0], a0); best[1] = fmaxf(best[1], a1);
            best[2] = fmaxf(best[2], a2); best[3] = fmaxf(best[3], a3);
            best[4] = fmaxf(best[4], a4);
        }
#pragma unroll
        for (int o = 0; o < 5; o++) {
            float v = best[o];
            g_p1[(b0 + li) * 845 + o * 169 + p] = make_float2(silu_f(v), tmap(v));
        }
    }
}

// ---------------- Kernel 2: conv5(Cin=5,O=5) split over outputs ----------------
// Instance NO=3 handles o=0..2 (coef rows 0..4124), NO=2 handles o=3..4.
// smem (bytes): wbh [0,2048) ; coefs float4 [2048, 68048) ; in float2 [68048, 108608)
#define K2_IMGS 6
#define K2_SMEM (2048 + 66000 + K2_IMGS * 845 * 8)
template <int NO>
__global__ void __launch_bounds__(512, 2)
k2_conv(int B, int coef_off, int wb_off, int o_base) {
    extern __shared__ __align__(16) char smraw[];
    float*  wbh = reinterpret_cast<float*>(smraw);            // 500
    float4* cs  = reinterpret_cast<float4*>(smraw + 2048);    // NO*1375
    float2* in  = reinterpret_cast<float2*>(smraw + 68048);   // 6*845
    int tid = threadIdx.x;
    int b0 = blockIdx.x * K2_IMGS;
    int nimg = min(K2_IMGS, B - b0);

    for (int i = tid; i < NO * 1375; i += 512) cs[i] = g_c2[coef_off + i];
    for (int i = tid; i < 500; i += 512) wbh[i] = g_wbT2s[wb_off + i];
    for (int i = tid; i < nimg * 845; i += 512) in[i] = g_p1[b0 * 845 + i];
    __syncthreads();

    int li = tid / 81, pos = tid % 81;
    if (li >= nimg) return;
    int oy = pos / 9, ox = pos % 9;

    float acc[NO];
#pragma unroll
    for (int o = 0; o < NO; o++) acc[o] = 0.0f;

    for (int c = 0; c < 5; c++) {
        const float2* inc = &in[li * 845 + c * 169];
        for (int kh = 0; kh < 5; kh++) {
            const float2* row = &inc[(oy + kh) * 13 + ox];
            int fbase = (c * 5 + kh) * 5;
#pragma unroll
            for (int kw = 0; kw < 5; kw++) {
                int f = fbase + kw;
                float2 st = row[kw];
                float4 wbv = *reinterpret_cast<const float4*>(&wbh[f * 4]);
                float wba[3] = {wbv.x, wbv.y, wbv.z};
#pragma unroll
                for (int o = 0; o < NO; o++) acc[o] += st.x * wba[o];
                float fj = floorf(st.y);
                int j = (int)fj;
                float u = st.y - fj;
                if ((unsigned)j <= 10u) {
                    int i0 = f * 11 + j;
#pragma unroll
                    for (int o = 0; o < NO; o++) acc[o] += cubic4(cs[i0 + o * 1375], u);
                }
            }
        }
    }
    int b = b0 + li;
#pragma unroll
    for (int o = 0; o < NO; o++) {
        float v = acc[o];
        g_p2[b * 405 + (o_base + o) * 81 + pos] = make_float2(silu_f(v), tmap(v));
    }
}

// ---------------- Kernel 3: conv3(Cin=5,O=2), 10 imgs/block -> g_h ----------------
// smem: c3s [0,15840); in [15840,48240); wbTs [48240,49680)
#define K3_IMGS 10
#define K3_SMEM (15840 + K3_IMGS * 405 * 8 + 1440)
__global__ void __launch_bounds__(512)
k3_conv(int B) {
    extern __shared__ __align__(16) char smraw3[];
    float4* c3s = reinterpret_cast<float4*>(smraw3);             // 990
    float2* in  = reinterpret_cast<float2*>(smraw3 + 15840);     // 10*405
    float*  wbTs = reinterpret_cast<float*>(smraw3 + 15840 + K3_IMGS * 405 * 8); // 360
    int tid = threadIdx.x;
    int b0 = blockIdx.x * K3_IMGS;
    int nimg = min(K3_IMGS, B - b0);

    for (int i = tid; i < 990; i += 512) c3s[i] = g_c3[i];
    for (int i = tid; i < 360; i += 512) wbTs[i] = g_wbT3[i];
    for (int i = tid; i < nimg * 405; i += 512) in[i] = g_p2[b0 * 405 + i];
    __syncthreads();

    for (int task = tid; task < nimg * 49; task += 512) {
        int li = task / 49, pos = task % 49;
        int oy = pos / 7, ox = pos % 7;
        float a0 = 0, a1 = 0;
        for (int c = 0; c < 5; c++) {
#pragma unroll
            for (int kh = 0; kh < 3; kh++)
#pragma unroll
            for (int kw = 0; kw < 3; kw++) {
                int f = (c * 3 + kh) * 3 + kw;
                float2 st = in[li * 405 + c * 81 + (oy + kh) * 9 + ox + kw];
                a0 += st.x * wbTs[f * 8 + 0];
                a1 += st.x * wbTs[f * 8 + 1];
                float fj = floorf(st.y);
                int j = (int)fj;
                float u = st.y - fj;
                if ((unsigned)j <= 10u) {
                    int i0 = f * 11 + j;
                    a0 += cubic4(c3s[i0], u);
                    a1 += cubic4(c3s[i0 + 495], u);
                }
            }
        }
        int b = b0 + li;
        g_h[b * 98 + pos]      = a0;   // flatten order o*49 + pos
        g_h[b * 98 + 49 + pos] = a1;
    }
}

// ---------------- Kernel 4: FC [B,98] @ [200,98]^T + b ----------------
// 200 threads, 16 imgs/block. fwT stored k-major [98][200]; thread computes 8 outputs.
// smem: fwT [0, 78400); h [78400, 84800) stride-100; fb [84800, 85600)
#define K4_IMGS 16
#define K4_SMEM (78400 + K4_IMGS * 100 * 4 + 800)
__global__ void __launch_bounds__(200)
k4_fc(const float* __restrict__ fcw, const float* __restrict__ fcb,
      float* __restrict__ out, int B) {
    extern __shared__ __align__(16) char smraw4[];
    float* fwT = reinterpret_cast<float*>(smraw4);           // 98*200
    float* h   = fwT + 98 * 200;                             // 16*100
    float* fb  = h + K4_IMGS * 100;                          // 200
    int tid = threadIdx.x;
    int b0 = blockIdx.x * K4_IMGS;
    int nimg = min(K4_IMGS, B - b0);

    for (int i = tid; i < 200 * 98; i += 200) {
        int o = i / 98, k = i % 98;
        fwT[k * 200 + o] = fcw[i];
    }
    fb[tid] = fcb[tid];
    for (int i = tid; i < nimg * 98; i += 200) {
        int img = i / 98, k = i % 98;
        h[img * 100 + k] = g_h[(b0 + img) * 98 + k];
    }
    __syncthreads();

    const float4* fwT4 = reinterpret_cast<const float4*>(fwT);
    const float4* fb4  = reinterpret_cast<const float4*>(fb);
    for (int t = tid; t < nimg * 25; t += 200) {
        int img = t / 25, og = t % 25;      // output group: columns og*8 .. og*8+7
        float4 a0 = fb4[og * 2];
        float4 a1 = fb4[og * 2 + 1];
        const float* hr = &h[img * 100];
#pragma unroll 2
        for (int k = 0; k < 98; k++) {
            float hv = hr[k];
            float4 w0 = fwT4[k * 50 + og * 2];
            float4 w1 = fwT4[k * 50 + og * 2 + 1];
            a0.x += hv * w0.x; a0.y += hv * w0.y; a0.z += hv * w0.z; a0.w += hv * w0.w;
            a1.x += hv * w1.x; a1.y += hv * w1.y; a1.z += hv * w1.z; a1.w += hv * w1.w;
        }
        float4* o4 = reinterpret_cast<float4*>(out + (b0 + img) * 200 + og * 8);
        o4[0] = a0;
        o4[1] = a1;
    }
}

extern "C" void kernel_launch(void* const* d_in, const int* in_sizes, int n_in,
                              void* d_out, int out_size) {
    const float* x   = (const float*)d_in[0];
    const float* wb1 = (const float*)d_in[1];
    const float* ws1 = (const float*)d_in[2];
    const float* wb2 = (const float*)d_in[3];
    const float* ws2 = (const float*)d_in[4];
    const float* wb3 = (const float*)d_in[5];
    const float* ws3 = (const float*)d_in[6];
    const float* fcw = (const float*)d_in[7];
    const float* fcb = (const float*)d_in[8];
    float* out = (float*)d_out;

    int B = in_sizes[0] / 784;

    cudaFuncSetAttribute(k2_conv<3>, cudaFuncAttributeMaxDynamicSharedMemorySize, K2_SMEM);
    cudaFuncSetAttribute(k2_conv<2>, cudaFuncAttributeMaxDynamicSharedMemorySize, K2_SMEM);
    cudaFuncSetAttribute(k3_conv,    cudaFuncAttributeMaxDynamicSharedMemorySize, K3_SMEM);
    cudaFuncSetAttribute(k4_fc,      cudaFuncAttributeMaxDynamicSharedMemorySize, K4_SMEM);

    build_tables<<<32, 256>>>(ws1, ws2, ws3, wb1, wb2, wb3);
    k1_conv_pool<<<(B + K1_IMGS - 1) / K1_IMGS, 256>>>(x, B);
    int g2 = (B + K2_IMGS - 1) / K2_IMGS;
    k2_conv<3><<<g2, 512, K2_SMEM>>>(B, 0, 0, 0);          // o = 0,1,2
    k2_conv<2><<<g2, 512, K2_SMEM>>>(B, 4125, 500, 3);     // o = 3,4
    k3_conv<<<(B + K3_IMGS - 1) / K3_IMGS, 512, K3_SMEM>>>(B);
    k4_fc<<<(B + K4_IMGS - 1) / K4_IMGS, 200, K4_SMEM>>>(fcw, fcb, out, B);
}

// round 7
// speedup vs baseline: 1.1479x; 1.1479x over previous
#include <cuda_runtime.h>
#include <math.h>

// ---------------- global scratch (allocation-free rule) ----------------
static __device__ float2 g_p1[4096 * 845];   // L1 pooled output as {silu, t}
static __device__ float2 g_p2[4096 * 405];   // L2 output as {silu, t}
static __device__ float  g_h[4096 * 98];     // L3 conv output (flattened)

__device__ __forceinline__ float silu_f(float x) {
    return __fdividef(x, 1.0f + __expf(-x));
}
__device__ __forceinline__ float tmap(float x) { return (x + 1.0f) * 2.5f + 3.0f; }
__device__ __forceinline__ float cubic4(float4 q, float u) {
    return ((q.w * u + q.z) * u + q.y) * u + q.x;
}

// Build one cubic-coefficient entry from raw spline weights (row-major [rows][8]).
__device__ __forceinline__ float4 coef_from_w(const float* __restrict__ ws, int row, int j) {
    float w[4];
#pragma unroll
    for (int k = 0; k < 4; k++) {
        int g = j - 3 + k;
        w[k] = (g >= 0 && g <= 7) ? __ldg(&ws[row * 8 + g]) : 0.0f;
    }
    const float s6 = 1.0f / 6.0f;
    float4 c;
    c.x = (w[0] + 4.0f * w[1] + w[2]) * s6;
    c.y = (w[2] - w[0]) * 0.5f;
    c.z = (w[0] - 2.0f * w[1] + w[2]) * 0.5f;
    c.w = (-w[0] + 3.0f * w[1] - 3.0f * w[2] + w[3]) * s6;
    return c;
}

// ---------------- Kernel 1: conv3(Cin=1,O=5) + maxpool2, 6 imgs, 512 thr ----------------
#define K1_IMGS 6
__global__ void __launch_bounds__(512)
k1_conv_pool(const float* __restrict__ x, const float* __restrict__ wb1,
             const float* __restrict__ ws1, int B) {
    __shared__ __align__(16) float wbTs[9 * 8];
    __shared__ float4 c1s[45 * 11];
    __shared__ float2 px[K1_IMGS * 784];
    int tid = threadIdx.x;
    int b0 = blockIdx.x * K1_IMGS;
    int nimg = min(K1_IMGS, B - b0);

    for (int i = tid; i < 45 * 11; i += 512) c1s[i] = coef_from_w(ws1, i / 11, i % 11);
    if (tid < 72) {
        int f = tid / 8, o = tid % 8;
        wbTs[tid] = (o < 5) ? __ldg(&wb1[o * 9 + f]) : 0.0f;
    }
    for (int i = tid; i < nimg * 784; i += 512) {
        float v = x[b0 * 784 + i];
        px[i] = make_float2(silu_f(v), tmap(v));
    }
    __syncthreads();

    for (int task = tid; task < nimg * 169; task += 512) {
        int li = task / 169, p = task % 169;
        int ph = p / 13, pw = p % 13;
        float best[5];
#pragma unroll
        for (int o = 0; o < 5; o++) best[o] = -3.0e38f;

        for (int d = 0; d < 4; d++) {
            int y = 2 * ph + (d >> 1), xx = 2 * pw + (d & 1);
            float a0 = 0, a1 = 0, a2 = 0, a3 = 0, a4 = 0;
#pragma unroll
            for (int r = 0; r < 3; r++)
#pragma unroll
            for (int c = 0; c < 3; c++) {
                int f = r * 3 + c;
                float2 st = px[li * 784 + (y + r) * 28 + xx + c];
                float4 wbv = *reinterpret_cast<const float4*>(&wbTs[f * 8]);
                float wb4 = wbTs[f * 8 + 4];
                a0 += st.x * wbv.x; a1 += st.x * wbv.y; a2 += st.x * wbv.z;
                a3 += st.x * wbv.w; a4 += st.x * wb4;
                float fj = floorf(st.y);
                int j = (int)fj;
                float u = st.y - fj;
                if ((unsigned)j <= 10u) {
                    int i0 = f * 11 + j;
                    a0 += cubic4(c1s[i0], u);
                    a1 += cubic4(c1s[i0 + 99], u);
                    a2 += cubic4(c1s[i0 + 198], u);
                    a3 += cubic4(c1s[i0 + 297], u);
                    a4 += cubic4(c1s[i0 + 396], u);
                }
            }
            best[0] = fmaxf(best[0], a0); best[1] = fmaxf(best[1], a1);
            best[2] = fmaxf(best[2], a2); best[3] = fmaxf(best[3], a3);
            best[4] = fmaxf(best[4], a4);
        }
#pragma unroll
        for (int o = 0; o < 5; o++) {
            float v = best[o];
            g_p1[(b0 + li) * 845 + o * 169 + p] = make_float2(silu_f(v), tmap(v));
        }
    }
}

// ---------------- Kernel 2: conv5(Cin=5,O=5) unified, 9 imgs, 768 thr ----------------
// smem (bytes): wbTs [0,4000); c2s float4 [4000,114000); in float2 [114000,174840)
#define K2_IMGS 9
#define K2_SMEM (4000 + 110000 + K2_IMGS * 845 * 8)
__global__ void __launch_bounds__(768)
k2_conv(const float* __restrict__ wb2, const float* __restrict__ ws2, int B) {
    extern __shared__ __align__(16) char smraw[];
    float*  wbTs = reinterpret_cast<float*>(smraw);                 // 1000
    float4* c2s  = reinterpret_cast<float4*>(smraw + 4000);         // 6875
    float2* in   = reinterpret_cast<float2*>(smraw + 114000);       // 9*845
    int tid = threadIdx.x;
    int b0 = blockIdx.x * K2_IMGS;
    int nimg = min(K2_IMGS, B - b0);

    for (int i = tid; i < 6875; i += 768) c2s[i] = coef_from_w(ws2, i / 11, i % 11);
    for (int i = tid; i < 1000; i += 768) {
        int f = i / 8, o = i % 8;
        wbTs[i] = (o < 5) ? __ldg(&wb2[o * 125 + f]) : 0.0f;
    }
    for (int i = tid; i < nimg * 845; i += 768) in[i] = g_p1[b0 * 845 + i];
    __syncthreads();

    int li = tid / 81, pos = tid % 81;
    if (li >= nimg) return;
    int oy = pos / 9, ox = pos % 9;

    float a0 = 0, a1 = 0, a2 = 0, a3 = 0, a4 = 0;
    for (int c = 0; c < 5; c++) {
        const float2* inc = &in[li * 845 + c * 169];
        for (int kh = 0; kh < 5; kh++) {
            const float2* row = &inc[(oy + kh) * 13 + ox];
            int fbase = (c * 5 + kh) * 5;
#pragma unroll
            for (int kw = 0; kw < 5; kw++) {
                int f = fbase + kw;
                float2 st = row[kw];
                float4 wbv = *reinterpret_cast<const float4*>(&wbTs[f * 8]);
                float wb4 = wbTs[f * 8 + 4];
                a0 += st.x * wbv.x; a1 += st.x * wbv.y; a2 += st.x * wbv.z;
                a3 += st.x * wbv.w; a4 += st.x * wb4;
                float fj = floorf(st.y);
                int j = (int)fj;
                float u = st.y - fj;
                if ((unsigned)j <= 10u) {
                    int i0 = f * 11 + j;
                    a0 += cubic4(c2s[i0], u);
                    a1 += cubic4(c2s[i0 + 1375], u);
                    a2 += cubic4(c2s[i0 + 2750], u);
                    a3 += cubic4(c2s[i0 + 4125], u);
                    a4 += cubic4(c2s[i0 + 5500], u);
                }
            }
        }
    }
    int b = b0 + li;
    float acc[5] = {a0, a1, a2, a3, a4};
#pragma unroll
    for (int o = 0; o < 5; o++) {
        float v = acc[o];
        g_p2[b * 405 + o * 81 + pos] = make_float2(silu_f(v), tmap(v));
    }
}

// ---------------- Kernel 3: conv3(Cin=5,O=2), 10 imgs, 512 thr -> g_h ----------------
// smem (bytes): c3s [0,15840); in [15840,48240); wbp float2 [48240,48600)
#define K3_IMGS 10
#define K3_SMEM (15840 + K3_IMGS * 405 * 8 + 45 * 8)
__global__ void __launch_bounds__(512)
k3_conv(const float* __restrict__ wb3, const float* __restrict__ ws3, int B) {
    extern __shared__ __align__(16) char smraw3[];
    float4* c3s = reinterpret_cast<float4*>(smraw3);             // 990
    float2* in  = reinterpret_cast<float2*>(smraw3 + 15840);     // 10*405
    float2* wbp = reinterpret_cast<float2*>(smraw3 + 15840 + K3_IMGS * 405 * 8); // 45
    int tid = threadIdx.x;
    int b0 = blockIdx.x * K3_IMGS;
    int nimg = min(K3_IMGS, B - b0);

    for (int i = tid; i < 990; i += 512) c3s[i] = coef_from_w(ws3, i / 11, i % 11);
    if (tid < 45) wbp[tid] = make_float2(__ldg(&wb3[tid]), __ldg(&wb3[45 + tid]));
    for (int i = tid; i < nimg * 405; i += 512) in[i] = g_p2[b0 * 405 + i];
    __syncthreads();

    for (int task = tid; task < nimg * 49; task += 512) {
        int li = task / 49, pos = task % 49;
        int oy = pos / 7, ox = pos % 7;
        float a0 = 0, a1 = 0;
        for (int c = 0; c < 5; c++) {
#pragma unroll
            for (int kh = 0; kh < 3; kh++)
#pragma unroll
            for (int kw = 0; kw < 3; kw++) {
                int f = (c * 3 + kh) * 3 + kw;
                float2 st = in[li * 405 + c * 81 + (oy + kh) * 9 + ox + kw];
                float2 wv = wbp[f];
                a0 += st.x * wv.x;
                a1 += st.x * wv.y;
                float fj = floorf(st.y);
                int j = (int)fj;
                float u = st.y - fj;
                if ((unsigned)j <= 10u) {
                    int i0 = f * 11 + j;
                    a0 += cubic4(c3s[i0], u);
                    a1 += cubic4(c3s[i0 + 495], u);
                }
            }
        }
        int b = b0 + li;
        g_h[b * 98 + pos]      = a0;   // flatten order o*49 + pos
        g_h[b * 98 + 49 + pos] = a1;
    }
}

// ---------------- Kernel 4: FC [B,98] @ [200,98]^T + b, 32 imgs, 256 thr ----------------
// smem: fwT k-major [98][200] [0,78400); h [78400,91200) stride-100; fb [91200,92000)
#define K4_IMGS 32
#define K4_SMEM (78400 + K4_IMGS * 100 * 4 + 800)
__global__ void __launch_bounds__(256)
k4_fc(const float* __restrict__ fcw, const float* __restrict__ fcb,
      float* __restrict__ out, int B) {
    extern __shared__ __align__(16) char smraw4[];
    float* fwT = reinterpret_cast<float*>(smraw4);           // 98*200
    float* h   = fwT + 98 * 200;                             // 32*100
    float* fb  = h + K4_IMGS * 100;                          // 200
    int tid = threadIdx.x;
    int b0 = blockIdx.x * K4_IMGS;
    int nimg = min(K4_IMGS, B - b0);

    for (int i = tid; i < 200 * 98; i += 256) {
        int o = i / 98, k = i % 98;
        fwT[k * 200 + o] = fcw[i];
    }
    if (tid < 200) fb[tid] = fcb[tid];
    for (int i = tid; i < nimg * 98; i += 256) {
        int img = i / 98, k = i % 98;
        h[img * 100 + k] = g_h[(b0 + img) * 98 + k];
    }
    __syncthreads();

    const float4* fwT4 = reinterpret_cast<const float4*>(fwT);
    const float4* fb4  = reinterpret_cast<const float4*>(fb);
    for (int t = tid; t < nimg * 25; t += 256) {
        int img = t / 25, og = t % 25;      // outputs og*8 .. og*8+7
        float4 a0 = fb4[og * 2];
        float4 a1 = fb4[og * 2 + 1];
        const float* hr = &h[img * 100];
#pragma unroll 2
        for (int k = 0; k < 98; k++) {
            float hv = hr[k];
            float4 w0 = fwT4[k * 50 + og * 2];
            float4 w1 = fwT4[k * 50 + og * 2 + 1];
            a0.x += hv * w0.x; a0.y += hv * w0.y; a0.z += hv * w0.z; a0.w += hv * w0.w;
            a1.x += hv * w1.x; a1.y += hv * w1.y; a1.z += hv * w1.z; a1.w += hv * w1.w;
        }
        float4* o4 = reinterpret_cast<float4*>(out + (b0 + img) * 200 + og * 8);
        o4[0] = a0;
        o4[1] = a1;
    }
}

extern "C" void kernel_launch(void* const* d_in, const int* in_sizes, int n_in,
                              void* d_out, int out_size) {
    const float* x   = (const float*)d_in[0];
    const float* wb1 = (const float*)d_in[1];
    const float* ws1 = (const float*)d_in[2];
    const float* wb2 = (const float*)d_in[3];
    const float* ws2 = (const float*)d_in[4];
    const float* wb3 = (const float*)d_in[5];
    const float* ws3 = (const float*)d_in[6];
    const float* fcw = (const float*)d_in[7];
    const float* fcb = (const float*)d_in[8];
    float* out = (float*)d_out;

    int B = in_sizes[0] / 784;

    cudaFuncSetAttribute(k2_conv, cudaFuncAttributeMaxDynamicSharedMemorySize, K2_SMEM);
    cudaFuncSetAttribute(k3_conv, cudaFuncAttributeMaxDynamicSharedMemorySize, K3_SMEM);
    cudaFuncSetAttribute(k4_fc,   cudaFuncAttributeMaxDynamicSharedMemorySize, K4_SMEM);

    k1_conv_pool<<<(B + K1_IMGS - 1) / K1_IMGS, 512>>>(x, wb1, ws1, B);
    k2_conv<<<(B + K2_IMGS - 1) / K2_IMGS, 768, K2_SMEM>>>(wb2, ws2, B);
    k3_conv<<<(B + K3_IMGS - 1) / K3_IMGS, 512, K3_SMEM>>>(wb3, ws3, B);
    k4_fc<<<(B + K4_IMGS - 1) / K4_IMGS, 256, K4_SMEM>>>(fcw, fcb, out, B);
}